// round 5
// baseline (speedup 1.0000x reference)
#include <cuda_runtime.h>
#include <cstdint>

#define SEQ    512
#define BATCH  1024
#define NTAG   64
#define NEGINF -10000.0f
#define DEPTH  8

__device__ __forceinline__ float ex2f_(float x) {
    float y; asm("ex2.approx.ftz.f32 %0, %1;" : "=f"(y) : "f"(x)); return y;
}
__device__ __forceinline__ float lg2f_(float x) {
    float y; asm("lg2.approx.ftz.f32 %0, %1;" : "=f"(y) : "f"(x)); return y;
}
__device__ __forceinline__ unsigned long long fma2_(unsigned long long a,
                                                    unsigned long long b,
                                                    unsigned long long c) {
    unsigned long long d;
    asm("fma.rn.f32x2 %0, %1, %2, %3;" : "=l"(d) : "l"(a), "l"(b), "l"(c));
    return d;
}
__device__ __forceinline__ unsigned long long add2_(unsigned long long a,
                                                    unsigned long long b) {
    unsigned long long d;
    asm("add.rn.f32x2 %0, %1, %2;" : "=l"(d) : "l"(a), "l"(b));
    return d;
}
__device__ __forceinline__ void unpack_(unsigned long long v, float& x, float& y) {
    asm("mov.b64 {%0, %1}, %2;" : "=f"(x), "=f"(y) : "l"(v));
}
__device__ __forceinline__ float wmax_(float v) {
#pragma unroll
    for (int d = 16; d; d >>= 1)
        v = fmaxf(v, __shfl_xor_sync(0xffffffffu, v, d));
    return v;
}
__device__ __forceinline__ uint32_t smem_u32_(const void* p) {
    uint32_t a;
    asm("{ .reg .u64 t; cvta.to.shared.u64 t, %1; cvt.u32.u64 %0, t; }"
        : "=r"(a) : "l"(p));
    return a;
}
__device__ __forceinline__ void cpa4_(uint32_t dst, const float* src) {
    asm volatile("cp.async.ca.shared.global [%0], [%1], 4;" :: "r"(dst), "l"(src));
}
__device__ __forceinline__ void cpa_commit_() {
    asm volatile("cp.async.commit_group;" ::: "memory");
}
__device__ __forceinline__ void cpa_wait_() {
    asm volatile("cp.async.wait_group %0;" :: "n"(DEPTH - 1) : "memory");
}

// One CTA = 64 threads = 2 warps = ONE batch. Thread tid owns tag j = tid.
// E row lives in 32 packed-f32x2 registers per thread. The p vector crosses
// warps via smem with one __syncthreads per step. Normalizer mu is the exact
// warp-pair max of alpha, lagged one step (overflow headroom e^+88 >> one-step
// growth ~e^10), exchanged through smem on the same barrier.
__global__ void __launch_bounds__(64)
crf_main(const float* __restrict__ feats,
         const float* __restrict__ mask,
         const float* __restrict__ trans,
         float* __restrict__ out) {
    const int tid  = threadIdx.x;        // tag index j
    const int lane = tid & 31;
    const int w    = tid >> 5;
    const int b    = blockIdx.x;

    __shared__ __align__(16) float ring[DEPTH][NTAG];   // 2 KB feats stream
    __shared__ __align__(16) float pbuf[2][NTAG];       // p, double buffered
    __shared__ float Mbuf[2][2];                        // per-warp alpha max
    __shared__ float red[2], mred[2], sred[2];

    const float LN2 = 0.6931471805599453f;
    const float L2E = 1.4426950408889634f;

    // --- prologue: start feats stream immediately (hide everything below) ---
    const uint32_t ring_u = smem_u32_(&ring[0][0]);
    const float*   fsrc   = feats + (size_t)b * NTAG + tid;  // step s at +s*65536
#pragma unroll
    for (int t = 0; t < DEPTH - 1; ++t) {
        cpa4_(ring_u + (t << 8) + tid * 4, fsrc + ((size_t)t << 16));
        cpa_commit_();
    }

    // E row for my tag, packed in i-pairs: E2[k] = (e^T[j][2k], e^T[j][2k+1])
    unsigned long long E2[32];
    {
        const float* tr = trans + tid * NTAG;
#pragma unroll
        for (int k = 0; k < 32; ++k) {
            const float e0 = __expf(tr[2 * k]);       // exp(-1e4) -> 0
            const float e1 = __expf(tr[2 * k + 1]);
            asm("mov.b64 %0, {%1, %2};" : "=l"(E2[k]) : "f"(e0), "f"(e1));
        }
    }
    const float tEnd = trans[NTAG + tid];             // transition[END=1][j]

    // len = sum of my batch's (monotone) mask column
    float ls = 0.0f;
#pragma unroll
    for (int t = 0; t < 8; ++t)
        ls += mask[(size_t)(t * 64 + tid) * BATCH + b];
#pragma unroll
    for (int d = 16; d; d >>= 1)
        ls += __shfl_xor_sync(0xffffffffu, ls, d);
    if (lane == 0) red[w] = ls;
    __syncthreads();
    const int len = (int)(red[0] + red[1] + 0.5f);

    float a    = (tid == 0) ? 0.0f : NEGINF;          // START_IDX = 0
    float mu   = 0.0f;                                // exact max(alpha_init)
    float Mloc = 0.0f;                                // warp max of prev alpha

#pragma unroll 2
    for (int s = 0; s < len; ++s) {
        const int ph = s & 1;

        // publish p_j = exp(a_j - mu) and this warp's previous alpha-max
        pbuf[ph][tid] = ex2f_(fmaf(a, L2E, -mu * L2E));
        if (lane == 0) Mbuf[ph][w] = Mloc;

        // stream feats: issue slot s+DEPTH-1 (clamped; dup tail writes are
        // byte-identical), retire slot s
        int sp = s + DEPTH - 1;
        if (sp > SEQ - 1) sp = SEQ - 1;
        cpa4_(ring_u + ((uint32_t)(sp & (DEPTH - 1)) << 8) + tid * 4,
              fsrc + ((size_t)sp << 16));
        cpa_commit_();
        cpa_wait_();
        __syncthreads();

        // next-step normalizer = exact max(alpha_{s-1}) across both warps
        const float mu_next = fmaxf(Mbuf[ph][0], Mbuf[ph][1]);
        const float fc = ring[s & (DEPTH - 1)][tid];

        // S_j = sum_i E[j,i] * p_i : 16 LDS.128 (broadcast) + 32 FFMA2
        const ulonglong2* pb = reinterpret_cast<const ulonglong2*>(&pbuf[ph][0]);
        unsigned long long x0 = 0ull, x1 = 0ull;
#pragma unroll
        for (int k = 0; k < 16; ++k) {
            const ulonglong2 q = pb[k];
            x0 = fma2_(E2[2 * k],     q.x, x0);
            x1 = fma2_(E2[2 * k + 1], q.y, x1);
        }
        float s0, s1;
        unpack_(add2_(x0, x1), s0, s1);
        const float S = s0 + s1;

        // alpha' = mu + f + log S (exact for any mu; floor kills the all-zero
        // START row's log(0))
        a = fmaf(lg2f_(fmaxf(S, 1e-37f)), LN2, mu + fc);

        Mloc = wmax_(a);          // for publication next step
        mu   = mu_next;
    }

    // out[b] = LSE_j( alpha_j + T[END][j] ), cross-warp combine via smem
    const float x = a + tEnd;
    const float m = wmax_(x);
    float ss = ex2f_(fmaf(x, L2E, -m * L2E));
#pragma unroll
    for (int d = 16; d; d >>= 1)
        ss += __shfl_xor_sync(0xffffffffu, ss, d);
    if (lane == 0) { mred[w] = m; sred[w] = ss; }
    __syncthreads();
    if (tid == 0) {
        const float m0 = mred[0], m1 = mred[1];
        const float mm = fmaxf(m0, m1);
        const float st = sred[0] * ex2f_((m0 - mm) * L2E) +
                         sred[1] * ex2f_((m1 - mm) * L2E);
        out[b] = fmaf(lg2f_(st), LN2, mm);
    }
}

extern "C" void kernel_launch(void* const* d_in, const int* in_sizes, int n_in,
                              void* d_out, int out_size) {
    const float* feats = nullptr;
    const float* maskp = nullptr;
    const float* trans = nullptr;
    for (int i = 0; i < n_in; ++i) {
        if (in_sizes[i] == SEQ * BATCH * NTAG)      feats = (const float*)d_in[i];
        else if (in_sizes[i] == SEQ * BATCH)        maskp = (const float*)d_in[i];
        else if (in_sizes[i] == NTAG * NTAG)        trans = (const float*)d_in[i];
    }
    crf_main<<<BATCH, 64>>>(feats, maskp, trans, (float*)d_out);
}

// round 6
// speedup vs baseline: 1.2328x; 1.2328x over previous
#include <cuda_runtime.h>
#include <cstdint>

#define SEQ    512
#define BATCH  1024
#define NTAG   64
#define NEGINF -10000.0f

__device__ __forceinline__ float ex2f_(float x) {
    float y; asm("ex2.approx.ftz.f32 %0, %1;" : "=f"(y) : "f"(x)); return y;
}
__device__ __forceinline__ float lg2f_(float x) {
    float y; asm("lg2.approx.ftz.f32 %0, %1;" : "=f"(y) : "f"(x)); return y;
}
__device__ __forceinline__ unsigned long long fma2_(unsigned long long a,
                                                    unsigned long long b,
                                                    unsigned long long c) {
    unsigned long long d;
    asm("fma.rn.f32x2 %0, %1, %2, %3;" : "=l"(d) : "l"(a), "l"(b), "l"(c));
    return d;
}
__device__ __forceinline__ unsigned long long add2_(unsigned long long a,
                                                    unsigned long long b) {
    unsigned long long d;
    asm("add.rn.f32x2 %0, %1, %2;" : "=l"(d) : "l"(a), "l"(b));
    return d;
}
__device__ __forceinline__ void unpack_(unsigned long long v, float& x, float& y) {
    asm("mov.b64 {%0, %1}, %2;" : "=f"(x), "=f"(y) : "l"(v));
}
__device__ __forceinline__ unsigned long long pack_(float x, float y) {
    unsigned long long r;
    asm("mov.b64 %0, {%1, %2};" : "=l"(r) : "f"(x), "f"(y));
    return r;
}
__device__ __forceinline__ float wmax_(float v) {
#pragma unroll
    for (int d = 16; d; d >>= 1)
        v = fmaxf(v, __shfl_xor_sync(0xffffffffu, v, d));
    return v;
}

// One warp = one batch; 4 independent warps per CTA (no __syncthreads).
// Lane l owns tags (l, l+32). E = exp(transition) rows resident in 128 regs.
// feats stream: direct LDG register pipeline, depth 4, rotated at compile time.
// Normalizer mu at step s = exact wmax(alpha_{s-1}), computed one step early
// (a full ~300-cycle slack), so no shuffle chain is on the critical path.
__global__ void __launch_bounds__(128)
crf_main(const float* __restrict__ feats,
         const float* __restrict__ mask,
         const float* __restrict__ trans,
         float* __restrict__ out) {
    const int lane = threadIdx.x & 31;
    const int w    = threadIdx.x >> 5;
    const int b    = blockIdx.x * 4 + w;

    __shared__ __align__(16) float pbuf[4][2][NTAG];   // [warp][phase][tag]

    const float LN2 = 0.6931471805599453f;
    const float L2E = 1.4426950408889634f;

    // ---- start the feats pipeline first (longest latency) ----
    const float* fs    = feats + (size_t)b * NTAG + lane;   // step s at +s*65536
    const float* flast = fs + ((size_t)(SEQ - 1) << 16);
    float fL[4], fH[4];
#pragma unroll
    for (int u = 0; u < 4; ++u) {
        const float* p = fs + ((size_t)u << 16);
        fL[u] = __ldcs(p);
        fH[u] = __ldcs(p + 32);
    }
    const float* fpre = fs + ((size_t)4 << 16);

    // ---- len = sum of this batch's monotone mask column ----
    float ls = 0.0f;
#pragma unroll
    for (int t = 0; t < 16; ++t)
        ls += __ldcs(mask + (size_t)(t * 32 + lane) * BATCH + b);
#pragma unroll
    for (int d = 16; d; d >>= 1)
        ls += __shfl_xor_sync(0xffffffffu, ls, d);
    const int len  = (int)(ls + 0.5f);
    const int lenr = (len + 3) & ~3;

    // ---- E rows for my two tags, packed in i-pairs (one-time 128 exps) ----
    unsigned long long EL[32], EH[32];
    {
        const float4* r0 = reinterpret_cast<const float4*>(trans + lane * NTAG);
        const float4* r1 = reinterpret_cast<const float4*>(trans + (lane + 32) * NTAG);
#pragma unroll
        for (int k = 0; k < 16; ++k) {
            const float4 t0 = r0[k];
            const float4 t1 = r1[k];
            EL[2 * k]     = pack_(__expf(t0.x), __expf(t0.y));  // exp(-1e4) -> 0
            EL[2 * k + 1] = pack_(__expf(t0.z), __expf(t0.w));
            EH[2 * k]     = pack_(__expf(t1.x), __expf(t1.y));
            EH[2 * k + 1] = pack_(__expf(t1.z), __expf(t1.w));
        }
    }
    const float tEnd_lo = trans[NTAG + lane];        // transition[END=1][j]
    const float tEnd_hi = trans[NTAG + 32 + lane];

    float a_lo = (lane == 0) ? 0.0f : NEGINF;        // START_IDX = 0
    float a_hi = NEGINF;
    float mu1  = 0.0f;                               // wmax(alpha_{s})   lagged
    float mu2  = 0.0f;                               // wmax(alpha_{s-1}) in use

#pragma unroll 1
    for (int s = 0; s < lenr; s += 4) {
#pragma unroll
        for (int u = 0; u < 4; ++u) {
            const int ph = u & 1;

            // p = exp(alpha - mu2); mu2 ready since the step before last
            const float c = -mu2 * L2E;
            pbuf[w][ph][lane]      = ex2f_(fmaf(a_lo, L2E, c));
            pbuf[w][ph][lane + 32] = ex2f_(fmaf(a_hi, L2E, c));
            __syncwarp();

            const float fc_lo = fL[u];
            const float fc_hi = fH[u];

            // prefetch step s+u+4 (clamped to last valid step)
            const float* pf = (fpre <= flast) ? fpre : flast;
            fL[u] = __ldcs(pf);
            fH[u] = __ldcs(pf + 32);
            fpre += (size_t)1 << 16;

            // S_j = sum_i E[j,i] p_i : 16 LDS.128 broadcast + 64 FFMA2
            const ulonglong2* pb =
                reinterpret_cast<const ulonglong2*>(&pbuf[w][ph][0]);
            unsigned long long x0 = 0ull, x1 = 0ull, y0 = 0ull, y1 = 0ull;
#pragma unroll
            for (int k = 0; k < 16; ++k) {
                const ulonglong2 q = pb[k];
                x0 = fma2_(EL[2 * k],     q.x, x0);
                x1 = fma2_(EL[2 * k + 1], q.y, x1);
                y0 = fma2_(EH[2 * k],     q.x, y0);
                y1 = fma2_(EH[2 * k + 1], q.y, y1);
            }
            float s0, s1, s2, s3;
            unpack_(add2_(x0, x1), s0, s1);
            unpack_(add2_(y0, y1), s2, s3);
            const float S_lo = s0 + s1;
            const float S_hi = s2 + s3;

            // alpha' = mu2 + f + log S (exact for any mu2; floor kills the
            // all-zero START row's log(0)); freeze past len via select
            const float n_lo = fmaf(lg2f_(fmaxf(S_lo, 1e-37f)), LN2, mu2 + fc_lo);
            const float n_hi = fmaf(lg2f_(fmaxf(S_hi, 1e-37f)), LN2, mu2 + fc_hi);
            const bool upd = (s + u) < len;
            a_lo = upd ? n_lo : a_lo;
            a_hi = upd ? n_hi : a_hi;

            // normalizer pipeline: result consumed two substeps from now
            mu2 = mu1;
            mu1 = wmax_(fmaxf(a_lo, a_hi));
        }
    }

    // out[b] = LSE_j( alpha_j + T[END][j] )
    const float x_lo = a_lo + tEnd_lo;
    const float x_hi = a_hi + tEnd_hi;
    const float m = wmax_(fmaxf(x_lo, x_hi));
    const float c = -m * L2E;
    float ss = ex2f_(fmaf(x_lo, L2E, c)) + ex2f_(fmaf(x_hi, L2E, c));
#pragma unroll
    for (int d = 16; d; d >>= 1)
        ss += __shfl_xor_sync(0xffffffffu, ss, d);
    if (lane == 0) out[b] = fmaf(lg2f_(ss), LN2, m);
}

extern "C" void kernel_launch(void* const* d_in, const int* in_sizes, int n_in,
                              void* d_out, int out_size) {
    const float* feats = nullptr;
    const float* maskp = nullptr;
    const float* trans = nullptr;
    for (int i = 0; i < n_in; ++i) {
        if (in_sizes[i] == SEQ * BATCH * NTAG)      feats = (const float*)d_in[i];
        else if (in_sizes[i] == SEQ * BATCH)        maskp = (const float*)d_in[i];
        else if (in_sizes[i] == NTAG * NTAG)        trans = (const float*)d_in[i];
    }
    crf_main<<<BATCH / 4, 128>>>(feats, maskp, trans, (float*)d_out);
}